// round 1
// baseline (speedup 1.0000x reference)
#include <cuda_runtime.h>
#include <math.h>

#define H_    4096
#define NH_   32
#define NKV_  8
#define HD_   128
#define S_    2048
#define B_    2
#define SCALE_ 0.08838834764831845f   // 128^-0.5

// ---------------- scratch (device globals; no allocations allowed) ----------
__device__ float g_qlin[(size_t)B_ * S_ * H_];            // 64 MB
__device__ float g_klin[(size_t)B_ * S_ * NKV_ * HD_];    // 16 MB
__device__ float g_vlin[(size_t)B_ * S_ * NKV_ * HD_];    // 16 MB
__device__ float g_q[(size_t)B_ * NH_ * S_ * HD_];        // 64 MB
__device__ float g_k[(size_t)B_ * NKV_ * S_ * HD_];       // 16 MB
__device__ float g_v[(size_t)B_ * NKV_ * S_ * HD_];       // 16 MB
__device__ float g_att[(size_t)B_ * S_ * H_];             // 64 MB

// ---------------- SGEMM: C[M,N] = A[M,K] @ B[N,K]^T (+bias) -----------------
#define BM 128
#define BN 128
#define BK 16

__global__ __launch_bounds__(256) void sgemm_bt(
    const float* __restrict__ A, const float* __restrict__ Bm,
    const float* __restrict__ bias, float* __restrict__ C,
    int M, int N, int K)
{
    __shared__ float As[BK][BM + 4];
    __shared__ float Bs[BK][BN + 4];
    int tid = threadIdx.x;
    int bm = blockIdx.y * BM, bn = blockIdx.x * BN;
    int ty = tid >> 4, tx = tid & 15;

    float acc[8][8];
#pragma unroll
    for (int i = 0; i < 8; i++)
#pragma unroll
        for (int j = 0; j < 8; j++) acc[i][j] = 0.f;

    for (int k0 = 0; k0 < K; k0 += BK) {
#pragma unroll
        for (int i = 0; i < 2; i++) {
            int idx = tid + i * 256;         // 512 float4 per operand tile
            int row = idx >> 2;
            int kc  = (idx & 3) << 2;
            float4 av = *(const float4*)(A + (size_t)(bm + row) * K + k0 + kc);
            As[kc + 0][row] = av.x; As[kc + 1][row] = av.y;
            As[kc + 2][row] = av.z; As[kc + 3][row] = av.w;
            float4 bv = *(const float4*)(Bm + (size_t)(bn + row) * K + k0 + kc);
            Bs[kc + 0][row] = bv.x; Bs[kc + 1][row] = bv.y;
            Bs[kc + 2][row] = bv.z; Bs[kc + 3][row] = bv.w;
        }
        __syncthreads();
#pragma unroll
        for (int k = 0; k < BK; k++) {
            float ra[8], rb[8];
            *(float4*)&ra[0] = *(float4*)&As[k][ty * 8];
            *(float4*)&ra[4] = *(float4*)&As[k][ty * 8 + 4];
            *(float4*)&rb[0] = *(float4*)&Bs[k][tx * 8];
            *(float4*)&rb[4] = *(float4*)&Bs[k][tx * 8 + 4];
#pragma unroll
            for (int i = 0; i < 8; i++)
#pragma unroll
                for (int j = 0; j < 8; j++) acc[i][j] += ra[i] * rb[j];
        }
        __syncthreads();
    }

#pragma unroll
    for (int i = 0; i < 8; i++) {
        int r = bm + ty * 8 + i;
#pragma unroll
        for (int j0 = 0; j0 < 8; j0 += 4) {
            float4 v;
            v.x = acc[i][j0]; v.y = acc[i][j0 + 1];
            v.z = acc[i][j0 + 2]; v.w = acc[i][j0 + 3];
            if (bias) {
                int c = bn + tx * 8 + j0;
                v.x += bias[c]; v.y += bias[c + 1]; v.z += bias[c + 2]; v.w += bias[c + 3];
            }
            *(float4*)(C + (size_t)r * N + bn + tx * 8 + j0) = v;
        }
    }
}

// ---------------- RoPE + head transpose:  [B,S,nh*HD] -> [B,nh,S,HD] --------
__global__ void rope_kernel(const float* __restrict__ X, const float* __restrict__ cs,
                            const float* __restrict__ sn, float* __restrict__ out,
                            int nheads)
{
    int idx = blockIdx.x * blockDim.x + threadIdx.x;  // over B*nheads*S*HD
    int d  = idx & (HD_ - 1);
    int s  = (idx >> 7) & (S_ - 1);
    int bh = idx >> 18;                 // /(HD*S)
    int h  = bh % nheads;
    int b  = bh / nheads;
    const float* xp = X + (size_t)(b * S_ + s) * (nheads * HD_) + h * HD_;
    int dd = d & 63;
    float c = cs[s * 64 + dd], si = sn[s * 64 + dd];
    float x1 = xp[2 * dd], x2 = xp[2 * dd + 1];
    out[idx] = (d < 64) ? (x1 * c - x2 * si) : (x1 * si + x2 * c);
}

// ---------------- V head transpose ------------------------------------------
__global__ void vtrans_kernel(const float* __restrict__ X, float* __restrict__ out)
{
    int idx = blockIdx.x * blockDim.x + threadIdx.x;  // over B*NKV*S*HD
    int d  = idx & (HD_ - 1);
    int s  = (idx >> 7) & (S_ - 1);
    int bh = idx >> 18;
    int h  = bh % NKV_;
    int b  = bh / NKV_;
    out[idx] = X[(size_t)(b * S_ + s) * (NKV_ * HD_) + h * HD_ + d];
}

// ---------------- Flash-style non-causal attention ---------------------------
#define BQ  64
#define BKV 64
#define KP  68     // padded k-dim for transposed K tile
#define PP  68     // padded P tile
#define ATT_SMEM ((BQ * HD_ + HD_ * KP + BKV * HD_ + BQ * PP) * 4)

__device__ __forceinline__ float warp16_max(float x) {
#pragma unroll
    for (int off = 8; off; off >>= 1)
        x = fmaxf(x, __shfl_xor_sync(0xffffffffu, x, off));
    return x;
}
__device__ __forceinline__ float warp16_sum(float x) {
#pragma unroll
    for (int off = 8; off; off >>= 1)
        x += __shfl_xor_sync(0xffffffffu, x, off);
    return x;
}

__global__ __launch_bounds__(256) void attn_kernel(
    const float* __restrict__ Q,  // [B,NH,S,HD] (pre-scaled applied here)
    const float* __restrict__ K,  // [B,NKV,S,HD]
    const float* __restrict__ V,  // [B,NKV,S,HD]
    float* __restrict__ O)        // [B,S,NH,HD]
{
    extern __shared__ float smb[];
    float* Qs  = smb;                  // BQ x HD
    float* Kst = Qs + BQ * HD_;        // HD x KP  (transposed K tile)
    float* Vs  = Kst + HD_ * KP;       // BKV x HD
    float* Ps  = Vs + BKV * HD_;       // BQ x PP

    int tid = threadIdx.x;
    int ty = tid >> 4, tx = tid & 15;  // 16x16 thread grid
    int qt = blockIdx.x, h = blockIdx.y, b = blockIdx.z;
    int kvh = h >> 2;                  // /N_REP
    const float* Qp = Q + (((size_t)b * NH_ + h) * S_ + qt * BQ) * HD_;
    const float* Kp = K + ((size_t)b * NKV_ + kvh) * S_ * HD_;
    const float* Vp = V + ((size_t)b * NKV_ + kvh) * S_ * HD_;

    // load Q tile (pre-scaled)
#pragma unroll
    for (int i = 0; i < 8; i++) {
        int fidx = tid + i * 256;            // 2048 float4
        int r = fidx >> 5, c4 = (fidx & 31) << 2;
        float4 v = *(const float4*)(Qp + r * HD_ + c4);
        v.x *= SCALE_; v.y *= SCALE_; v.z *= SCALE_; v.w *= SCALE_;
        *(float4*)&Qs[r * HD_ + c4] = v;
    }

    float m[4], l[4], acc[4][8];
#pragma unroll
    for (int qi = 0; qi < 4; qi++) {
        m[qi] = -1e30f; l[qi] = 0.f;
#pragma unroll
        for (int c = 0; c < 8; c++) acc[qi][c] = 0.f;
    }

    for (int kt = 0; kt < S_ / BKV; kt++) {
        __syncthreads();   // prior PV done before overwriting tiles
        const float* Kt = Kp + (size_t)kt * BKV * HD_;
#pragma unroll
        for (int i = 0; i < 8; i++) {       // K tile, transposed into smem
            int fidx = tid + i * 256;
            int r = fidx & 63, d4 = (fidx >> 6) << 2;
            float4 v = *(const float4*)(Kt + r * HD_ + d4);
            Kst[(d4 + 0) * KP + r] = v.x;
            Kst[(d4 + 1) * KP + r] = v.y;
            Kst[(d4 + 2) * KP + r] = v.z;
            Kst[(d4 + 3) * KP + r] = v.w;
        }
        const float* Vt = Vp + (size_t)kt * BKV * HD_;
#pragma unroll
        for (int i = 0; i < 8; i++) {       // V tile
            int fidx = tid + i * 256;
            int r = fidx >> 5, c4 = (fidx & 31) << 2;
            *(float4*)&Vs[r * HD_ + c4] = *(const float4*)(Vt + r * HD_ + c4);
        }
        __syncthreads();

        // ---- scores: 4q x 4k per thread over HD=128 ----
        float s4[4][4];
#pragma unroll
        for (int qi = 0; qi < 4; qi++)
#pragma unroll
            for (int kj = 0; kj < 4; kj++) s4[qi][kj] = 0.f;

        for (int d0 = 0; d0 < HD_; d0 += 4) {
            float qa[4][4], ka[4][4];
#pragma unroll
            for (int qi = 0; qi < 4; qi++) {
                float4 t = *(float4*)&Qs[(ty * 4 + qi) * HD_ + d0];
                qa[qi][0] = t.x; qa[qi][1] = t.y; qa[qi][2] = t.z; qa[qi][3] = t.w;
            }
#pragma unroll
            for (int dd = 0; dd < 4; dd++) {
                float4 t = *(float4*)&Kst[(d0 + dd) * KP + tx * 4];
                ka[dd][0] = t.x; ka[dd][1] = t.y; ka[dd][2] = t.z; ka[dd][3] = t.w;
            }
#pragma unroll
            for (int qi = 0; qi < 4; qi++)
#pragma unroll
                for (int kj = 0; kj < 4; kj++)
#pragma unroll
                    for (int dd = 0; dd < 4; dd++)
                        s4[qi][kj] += qa[qi][dd] * ka[dd][kj];
        }

        // ---- online softmax update ----
#pragma unroll
        for (int qi = 0; qi < 4; qi++) {
            float mt = fmaxf(fmaxf(s4[qi][0], s4[qi][1]), fmaxf(s4[qi][2], s4[qi][3]));
            mt = warp16_max(mt);
            float mn = fmaxf(m[qi], mt);
            float corr = __expf(m[qi] - mn);
            float rs = 0.f;
#pragma unroll
            for (int kj = 0; kj < 4; kj++) {
                float p = __expf(s4[qi][kj] - mn);
                Ps[(ty * 4 + qi) * PP + tx * 4 + kj] = p;
                rs += p;
            }
            rs = warp16_sum(rs);
            l[qi] = l[qi] * corr + rs;
            m[qi] = mn;
#pragma unroll
            for (int c = 0; c < 8; c++) acc[qi][c] *= corr;
        }
        __syncthreads();

        // ---- PV: O += P @ V ----
#pragma unroll 4
        for (int j = 0; j < BKV; j++) {
            float p0 = Ps[(ty * 4 + 0) * PP + j];
            float p1 = Ps[(ty * 4 + 1) * PP + j];
            float p2 = Ps[(ty * 4 + 2) * PP + j];
            float p3 = Ps[(ty * 4 + 3) * PP + j];
            float4 v0 = *(float4*)&Vs[j * HD_ + tx * 8];
            float4 v1 = *(float4*)&Vs[j * HD_ + tx * 8 + 4];
            acc[0][0] += p0 * v0.x; acc[0][1] += p0 * v0.y; acc[0][2] += p0 * v0.z; acc[0][3] += p0 * v0.w;
            acc[0][4] += p0 * v1.x; acc[0][5] += p0 * v1.y; acc[0][6] += p0 * v1.z; acc[0][7] += p0 * v1.w;
            acc[1][0] += p1 * v0.x; acc[1][1] += p1 * v0.y; acc[1][2] += p1 * v0.z; acc[1][3] += p1 * v0.w;
            acc[1][4] += p1 * v1.x; acc[1][5] += p1 * v1.y; acc[1][6] += p1 * v1.z; acc[1][7] += p1 * v1.w;
            acc[2][0] += p2 * v0.x; acc[2][1] += p2 * v0.y; acc[2][2] += p2 * v0.z; acc[2][3] += p2 * v0.w;
            acc[2][4] += p2 * v1.x; acc[2][5] += p2 * v1.y; acc[2][6] += p2 * v1.z; acc[2][7] += p2 * v1.w;
            acc[3][0] += p3 * v0.x; acc[3][1] += p3 * v0.y; acc[3][2] += p3 * v0.z; acc[3][3] += p3 * v0.w;
            acc[3][4] += p3 * v1.x; acc[3][5] += p3 * v1.y; acc[3][6] += p3 * v1.z; acc[3][7] += p3 * v1.w;
        }
    }

    // ---- epilogue: normalize + write [B,S,NH,HD] ----
#pragma unroll
    for (int qi = 0; qi < 4; qi++) {
        float inv = 1.f / l[qi];
        int srow = qt * BQ + ty * 4 + qi;
        float* op = O + (((size_t)b * S_ + srow) * NH_ + h) * HD_ + tx * 8;
        float4 o0, o1;
        o0.x = acc[qi][0] * inv; o0.y = acc[qi][1] * inv;
        o0.z = acc[qi][2] * inv; o0.w = acc[qi][3] * inv;
        o1.x = acc[qi][4] * inv; o1.y = acc[qi][5] * inv;
        o1.z = acc[qi][6] * inv; o1.w = acc[qi][7] * inv;
        *(float4*)op = o0;
        *(float4*)(op + 4) = o1;
    }
}

// ---------------- launcher ---------------------------------------------------
extern "C" void kernel_launch(void* const* d_in, const int* in_sizes, int n_in,
                              void* d_out, int out_size)
{
    const float* hs   = (const float*)d_in[0];
    const float* cosb = (const float*)d_in[1];
    const float* sinb = (const float*)d_in[2];
    const float* Wq   = (const float*)d_in[3];
    const float* Wk   = (const float*)d_in[4];
    const float* bk   = (const float*)d_in[5];
    const float* Wv   = (const float*)d_in[6];
    const float* bv   = (const float*)d_in[7];
    const float* Wo   = (const float*)d_in[8];
    float* out = (float*)d_out;

    float *qlin, *klin, *vlin, *q, *k, *v, *att;
    cudaGetSymbolAddress((void**)&qlin, g_qlin);
    cudaGetSymbolAddress((void**)&klin, g_klin);
    cudaGetSymbolAddress((void**)&vlin, g_vlin);
    cudaGetSymbolAddress((void**)&q,    g_q);
    cudaGetSymbolAddress((void**)&k,    g_k);
    cudaGetSymbolAddress((void**)&v,    g_v);
    cudaGetSymbolAddress((void**)&att,  g_att);

    const int M = B_ * S_;  // 4096 tokens

    // projections
    sgemm_bt<<<dim3(H_ / BN, M / BM), 256>>>(hs, Wq, nullptr, qlin, M, H_, H_);
    sgemm_bt<<<dim3((NKV_ * HD_) / BN, M / BM), 256>>>(hs, Wk, bk, klin, M, NKV_ * HD_, H_);
    sgemm_bt<<<dim3((NKV_ * HD_) / BN, M / BM), 256>>>(hs, Wv, bv, vlin, M, NKV_ * HD_, H_);

    // rope + layout
    rope_kernel<<<(B_ * NH_ * S_ * HD_) / 256, 256>>>(qlin, cosb, sinb, q, NH_);
    rope_kernel<<<(B_ * NKV_ * S_ * HD_) / 256, 256>>>(klin, cosb, sinb, k, NKV_);
    vtrans_kernel<<<(B_ * NKV_ * S_ * HD_) / 256, 256>>>(vlin, v);

    // attention
    cudaFuncSetAttribute(attn_kernel, cudaFuncAttributeMaxDynamicSharedMemorySize, ATT_SMEM);
    attn_kernel<<<dim3(S_ / BQ, NH_, B_), 256, ATT_SMEM>>>(q, k, v, att);

    // output projection
    sgemm_bt<<<dim3(H_ / BN, M / BM), 256>>>(att, Wo, nullptr, out, M, H_, H_);
}

// round 2
// speedup vs baseline: 1.6519x; 1.6519x over previous
#include <cuda_runtime.h>
#include <math.h>

#define H_    4096
#define NH_   32
#define NKV_  8
#define HD_   128
#define S_    2048
#define B_    2
#define SCALE_ 0.08838834764831845f   // 128^-0.5

// ---------------- scratch (device globals; no allocations allowed) ----------
__device__ float g_qlin[(size_t)B_ * S_ * H_];            // 64 MB
__device__ float g_klin[(size_t)B_ * S_ * NKV_ * HD_];    // 16 MB
__device__ float g_vlin[(size_t)B_ * S_ * NKV_ * HD_];    // 16 MB
__device__ float g_q[(size_t)B_ * NH_ * S_ * HD_];        // 64 MB
__device__ float g_k[(size_t)B_ * NKV_ * S_ * HD_];       // 16 MB
__device__ float g_v[(size_t)B_ * NKV_ * S_ * HD_];       // 16 MB
__device__ float g_att[(size_t)B_ * S_ * H_];             // 64 MB

// ---------------- tf32 helpers ----------------------------------------------
__device__ __forceinline__ unsigned f2tf32(float f) {
    unsigned r;
    asm("cvt.rna.tf32.f32 %0, %1;" : "=r"(r) : "f"(f));
    return r;
}

__device__ __forceinline__ void mma_tf32(float c[4], const unsigned a[4], const unsigned b[2]) {
    asm volatile(
        "mma.sync.aligned.m16n8k8.row.col.f32.tf32.tf32.f32 "
        "{%0,%1,%2,%3}, {%4,%5,%6,%7}, {%8,%9}, {%0,%1,%2,%3};\n"
        : "+f"(c[0]), "+f"(c[1]), "+f"(c[2]), "+f"(c[3])
        : "r"(a[0]), "r"(a[1]), "r"(a[2]), "r"(a[3]), "r"(b[0]), "r"(b[1]));
}

// ---------------- TF32 GEMM: C[M,N] = A[M,K] @ B[N,K]^T (+bias) -------------
// block tile 128x128, k-tile 16, 256 threads = 8 warps (2m x 4n), warp 64x32
#define SAS 20   // smem row stride (words); conflict-free for frag pattern

__global__ __launch_bounds__(256) void gemm_tf32(
    const float* __restrict__ A, const float* __restrict__ Bm,
    const float* __restrict__ bias, float* __restrict__ C,
    int M, int N, int K)
{
    __shared__ unsigned As[128 * SAS];
    __shared__ unsigned Bs[128 * SAS];

    int tid = threadIdx.x;
    int warp = tid >> 5, lane = tid & 31;
    int r = lane >> 2, cq = lane & 3;
    int wm = (warp >> 2) * 64, wn = (warp & 3) * 32;
    int bm = blockIdx.y * 128, bn = blockIdx.x * 128;

    float acc[4][4][4];
#pragma unroll
    for (int mi = 0; mi < 4; mi++)
#pragma unroll
        for (int ni = 0; ni < 4; ni++)
#pragma unroll
            for (int t = 0; t < 4; t++) acc[mi][ni][t] = 0.f;

    // global load indices: 512 float4 per operand tile, 2 per thread
    int row0 = tid >> 2,        c40 = (tid & 3) << 2;
    int row1 = (tid + 256) >> 2, c41 = ((tid + 256) & 3) << 2;

    const float* Ab = A + (size_t)bm * K;
    const float* Bb = Bm + (size_t)bn * K;

    float4 pa0, pa1, pb0, pb1;
    pa0 = *(const float4*)(Ab + (size_t)row0 * K + c40);
    pa1 = *(const float4*)(Ab + (size_t)row1 * K + c41);
    pb0 = *(const float4*)(Bb + (size_t)row0 * K + c40);
    pb1 = *(const float4*)(Bb + (size_t)row1 * K + c41);

    int ntiles = K >> 4;
    for (int kt = 0; kt < ntiles; kt++) {
        // store prefetched tile to smem with tf32 conversion
        As[row0 * SAS + c40 + 0] = f2tf32(pa0.x);
        As[row0 * SAS + c40 + 1] = f2tf32(pa0.y);
        As[row0 * SAS + c40 + 2] = f2tf32(pa0.z);
        As[row0 * SAS + c40 + 3] = f2tf32(pa0.w);
        As[row1 * SAS + c41 + 0] = f2tf32(pa1.x);
        As[row1 * SAS + c41 + 1] = f2tf32(pa1.y);
        As[row1 * SAS + c41 + 2] = f2tf32(pa1.z);
        As[row1 * SAS + c41 + 3] = f2tf32(pa1.w);
        Bs[row0 * SAS + c40 + 0] = f2tf32(pb0.x);
        Bs[row0 * SAS + c40 + 1] = f2tf32(pb0.y);
        Bs[row0 * SAS + c40 + 2] = f2tf32(pb0.z);
        Bs[row0 * SAS + c40 + 3] = f2tf32(pb0.w);
        Bs[row1 * SAS + c41 + 0] = f2tf32(pb1.x);
        Bs[row1 * SAS + c41 + 1] = f2tf32(pb1.y);
        Bs[row1 * SAS + c41 + 2] = f2tf32(pb1.z);
        Bs[row1 * SAS + c41 + 3] = f2tf32(pb1.w);
        __syncthreads();

        // prefetch next tile (overlaps with mma below)
        if (kt + 1 < ntiles) {
            int k0 = (kt + 1) << 4;
            pa0 = *(const float4*)(Ab + (size_t)row0 * K + k0 + c40);
            pa1 = *(const float4*)(Ab + (size_t)row1 * K + k0 + c41);
            pb0 = *(const float4*)(Bb + (size_t)row0 * K + k0 + c40);
            pb1 = *(const float4*)(Bb + (size_t)row1 * K + k0 + c41);
        }

#pragma unroll
        for (int s = 0; s < 2; s++) {
            unsigned a[4][4], b[4][2];
#pragma unroll
            for (int mi = 0; mi < 4; mi++) {
                int base = (wm + mi * 16 + r) * SAS + s * 8 + cq;
                a[mi][0] = As[base];
                a[mi][1] = As[base + 8 * SAS];
                a[mi][2] = As[base + 4];
                a[mi][3] = As[base + 8 * SAS + 4];
            }
#pragma unroll
            for (int ni = 0; ni < 4; ni++) {
                int base = (wn + ni * 8 + r) * SAS + s * 8 + cq;
                b[ni][0] = Bs[base];
                b[ni][1] = Bs[base + 4];
            }
#pragma unroll
            for (int mi = 0; mi < 4; mi++)
#pragma unroll
                for (int ni = 0; ni < 4; ni++)
                    mma_tf32(acc[mi][ni], a[mi], b[ni]);
        }
        __syncthreads();
    }

    // epilogue
#pragma unroll
    for (int mi = 0; mi < 4; mi++) {
#pragma unroll
        for (int ni = 0; ni < 4; ni++) {
            int row = bm + wm + mi * 16 + r;
            int col = bn + wn + ni * 8 + cq * 2;
            float b0 = 0.f, b1 = 0.f;
            if (bias) { b0 = bias[col]; b1 = bias[col + 1]; }
            float2 v0, v1;
            v0.x = acc[mi][ni][0] + b0; v0.y = acc[mi][ni][1] + b1;
            v1.x = acc[mi][ni][2] + b0; v1.y = acc[mi][ni][3] + b1;
            *(float2*)(C + (size_t)row * N + col) = v0;
            *(float2*)(C + (size_t)(row + 8) * N + col) = v1;
        }
    }
}

// ---------------- RoPE + head transpose:  [B,S,nh*HD] -> [B,nh,S,HD] --------
__global__ void rope_kernel(const float* __restrict__ X, const float* __restrict__ cs,
                            const float* __restrict__ sn, float* __restrict__ out,
                            int nheads)
{
    int idx = blockIdx.x * blockDim.x + threadIdx.x;  // over B*nheads*S*HD
    int d  = idx & (HD_ - 1);
    int s  = (idx >> 7) & (S_ - 1);
    int bh = idx >> 18;                 // /(HD*S)
    int h  = bh % nheads;
    int b  = bh / nheads;
    const float* xp = X + (size_t)(b * S_ + s) * (nheads * HD_) + h * HD_;
    int dd = d & 63;
    float c = cs[s * 64 + dd], si = sn[s * 64 + dd];
    float x1 = xp[2 * dd], x2 = xp[2 * dd + 1];
    out[idx] = (d < 64) ? (x1 * c - x2 * si) : (x1 * si + x2 * c);
}

// ---------------- V head transpose ------------------------------------------
__global__ void vtrans_kernel(const float* __restrict__ X, float* __restrict__ out)
{
    int idx = blockIdx.x * blockDim.x + threadIdx.x;  // over B*NKV*S*HD
    int d  = idx & (HD_ - 1);
    int s  = (idx >> 7) & (S_ - 1);
    int bh = idx >> 18;
    int h  = bh % NKV_;
    int b  = bh / NKV_;
    out[idx] = X[(size_t)(b * S_ + s) * (NKV_ * HD_) + h * HD_ + d];
}

// ---------------- Flash-style non-causal attention ---------------------------
#define BQ  64
#define BKV 64
#define KP  68     // padded k-dim for transposed K tile
#define PP  68     // padded P tile
#define ATT_SMEM ((BQ * HD_ + HD_ * KP + BKV * HD_ + BQ * PP) * 4)

__device__ __forceinline__ float warp16_max(float x) {
#pragma unroll
    for (int off = 8; off; off >>= 1)
        x = fmaxf(x, __shfl_xor_sync(0xffffffffu, x, off));
    return x;
}
__device__ __forceinline__ float warp16_sum(float x) {
#pragma unroll
    for (int off = 8; off; off >>= 1)
        x += __shfl_xor_sync(0xffffffffu, x, off);
    return x;
}

__global__ __launch_bounds__(256) void attn_kernel(
    const float* __restrict__ Q,  // [B,NH,S,HD]
    const float* __restrict__ K,  // [B,NKV,S,HD]
    const float* __restrict__ V,  // [B,NKV,S,HD]
    float* __restrict__ O)        // [B,S,NH,HD]
{
    extern __shared__ float smb[];
    float* Qs  = smb;                  // BQ x HD
    float* Kst = Qs + BQ * HD_;        // HD x KP  (transposed K tile)
    float* Vs  = Kst + HD_ * KP;       // BKV x HD
    float* Ps  = Vs + BKV * HD_;       // BQ x PP

    int tid = threadIdx.x;
    int ty = tid >> 4, tx = tid & 15;  // 16x16 thread grid
    int qt = blockIdx.x, h = blockIdx.y, b = blockIdx.z;
    int kvh = h >> 2;                  // /N_REP
    const float* Qp = Q + (((size_t)b * NH_ + h) * S_ + qt * BQ) * HD_;
    const float* Kp = K + ((size_t)b * NKV_ + kvh) * S_ * HD_;
    const float* Vp = V + ((size_t)b * NKV_ + kvh) * S_ * HD_;

    // load Q tile (pre-scaled)
#pragma unroll
    for (int i = 0; i < 8; i++) {
        int fidx = tid + i * 256;            // 2048 float4
        int rr = fidx >> 5, c4 = (fidx & 31) << 2;
        float4 v = *(const float4*)(Qp + rr * HD_ + c4);
        v.x *= SCALE_; v.y *= SCALE_; v.z *= SCALE_; v.w *= SCALE_;
        *(float4*)&Qs[rr * HD_ + c4] = v;
    }

    float m[4], l[4], acc[4][8];
#pragma unroll
    for (int qi = 0; qi < 4; qi++) {
        m[qi] = -1e30f; l[qi] = 0.f;
#pragma unroll
        for (int c = 0; c < 8; c++) acc[qi][c] = 0.f;
    }

    for (int kt = 0; kt < S_ / BKV; kt++) {
        __syncthreads();   // prior PV done before overwriting tiles
        const float* Kt = Kp + (size_t)kt * BKV * HD_;
#pragma unroll
        for (int i = 0; i < 8; i++) {       // K tile, transposed into smem
            int fidx = tid + i * 256;
            int rr = fidx & 63, d4 = (fidx >> 6) << 2;
            float4 v = *(const float4*)(Kt + rr * HD_ + d4);
            Kst[(d4 + 0) * KP + rr] = v.x;
            Kst[(d4 + 1) * KP + rr] = v.y;
            Kst[(d4 + 2) * KP + rr] = v.z;
            Kst[(d4 + 3) * KP + rr] = v.w;
        }
        const float* Vt = Vp + (size_t)kt * BKV * HD_;
#pragma unroll
        for (int i = 0; i < 8; i++) {       // V tile
            int fidx = tid + i * 256;
            int rr = fidx >> 5, c4 = (fidx & 31) << 2;
            *(float4*)&Vs[rr * HD_ + c4] = *(const float4*)(Vt + rr * HD_ + c4);
        }
        __syncthreads();

        // ---- scores: 4q x 4k per thread over HD=128 ----
        float s4[4][4];
#pragma unroll
        for (int qi = 0; qi < 4; qi++)
#pragma unroll
            for (int kj = 0; kj < 4; kj++) s4[qi][kj] = 0.f;

        for (int d0 = 0; d0 < HD_; d0 += 4) {
            float qa[4][4], ka[4][4];
#pragma unroll
            for (int qi = 0; qi < 4; qi++) {
                float4 t = *(float4*)&Qs[(ty * 4 + qi) * HD_ + d0];
                qa[qi][0] = t.x; qa[qi][1] = t.y; qa[qi][2] = t.z; qa[qi][3] = t.w;
            }
#pragma unroll
            for (int dd = 0; dd < 4; dd++) {
                float4 t = *(float4*)&Kst[(d0 + dd) * KP + tx * 4];
                ka[dd][0] = t.x; ka[dd][1] = t.y; ka[dd][2] = t.z; ka[dd][3] = t.w;
            }
#pragma unroll
            for (int qi = 0; qi < 4; qi++)
#pragma unroll
                for (int kj = 0; kj < 4; kj++)
#pragma unroll
                    for (int dd = 0; dd < 4; dd++)
                        s4[qi][kj] += qa[qi][dd] * ka[dd][kj];
        }

        // ---- online softmax update ----
#pragma unroll
        for (int qi = 0; qi < 4; qi++) {
            float mt = fmaxf(fmaxf(s4[qi][0], s4[qi][1]), fmaxf(s4[qi][2], s4[qi][3]));
            mt = warp16_max(mt);
            float mn = fmaxf(m[qi], mt);
            float corr = __expf(m[qi] - mn);
            float rs = 0.f;
#pragma unroll
            for (int kj = 0; kj < 4; kj++) {
                float p = __expf(s4[qi][kj] - mn);
                Ps[(ty * 4 + qi) * PP + tx * 4 + kj] = p;
                rs += p;
            }
            rs = warp16_sum(rs);
            l[qi] = l[qi] * corr + rs;
            m[qi] = mn;
#pragma unroll
            for (int c = 0; c < 8; c++) acc[qi][c] *= corr;
        }
        __syncthreads();

        // ---- PV: O += P @ V ----
#pragma unroll 4
        for (int j = 0; j < BKV; j++) {
            float p0 = Ps[(ty * 4 + 0) * PP + j];
            float p1 = Ps[(ty * 4 + 1) * PP + j];
            float p2 = Ps[(ty * 4 + 2) * PP + j];
            float p3 = Ps[(ty * 4 + 3) * PP + j];
            float4 v0 = *(float4*)&Vs[j * HD_ + tx * 8];
            float4 v1 = *(float4*)&Vs[j * HD_ + tx * 8 + 4];
            acc[0][0] += p0 * v0.x; acc[0][1] += p0 * v0.y; acc[0][2] += p0 * v0.z; acc[0][3] += p0 * v0.w;
            acc[0][4] += p0 * v1.x; acc[0][5] += p0 * v1.y; acc[0][6] += p0 * v1.z; acc[0][7] += p0 * v1.w;
            acc[1][0] += p1 * v0.x; acc[1][1] += p1 * v0.y; acc[1][2] += p1 * v0.z; acc[1][3] += p1 * v0.w;
            acc[1][4] += p1 * v1.x; acc[1][5] += p1 * v1.y; acc[1][6] += p1 * v1.z; acc[1][7] += p1 * v1.w;
            acc[2][0] += p2 * v0.x; acc[2][1] += p2 * v0.y; acc[2][2] += p2 * v0.z; acc[2][3] += p2 * v0.w;
            acc[2][4] += p2 * v1.x; acc[2][5] += p2 * v1.y; acc[2][6] += p2 * v1.z; acc[2][7] += p2 * v1.w;
            acc[3][0] += p3 * v0.x; acc[3][1] += p3 * v0.y; acc[3][2] += p3 * v0.z; acc[3][3] += p3 * v0.w;
            acc[3][4] += p3 * v1.x; acc[3][5] += p3 * v1.y; acc[3][6] += p3 * v1.z; acc[3][7] += p3 * v1.w;
        }
    }

    // ---- epilogue: normalize + write [B,S,NH,HD] ----
#pragma unroll
    for (int qi = 0; qi < 4; qi++) {
        float inv = 1.f / l[qi];
        int srow = qt * BQ + ty * 4 + qi;
        float* op = O + (((size_t)b * S_ + srow) * NH_ + h) * HD_ + tx * 8;
        float4 o0, o1;
        o0.x = acc[qi][0] * inv; o0.y = acc[qi][1] * inv;
        o0.z = acc[qi][2] * inv; o0.w = acc[qi][3] * inv;
        o1.x = acc[qi][4] * inv; o1.y = acc[qi][5] * inv;
        o1.z = acc[qi][6] * inv; o1.w = acc[qi][7] * inv;
        *(float4*)op = o0;
        *(float4*)(op + 4) = o1;
    }
}

// ---------------- launcher ---------------------------------------------------
extern "C" void kernel_launch(void* const* d_in, const int* in_sizes, int n_in,
                              void* d_out, int out_size)
{
    const float* hs   = (const float*)d_in[0];
    const float* cosb = (const float*)d_in[1];
    const float* sinb = (const float*)d_in[2];
    const float* Wq   = (const float*)d_in[3];
    const float* Wk   = (const float*)d_in[4];
    const float* bk   = (const float*)d_in[5];
    const float* Wv   = (const float*)d_in[6];
    const float* bv   = (const float*)d_in[7];
    const float* Wo   = (const float*)d_in[8];
    float* out = (float*)d_out;

    float *qlin, *klin, *vlin, *q, *k, *v, *att;
    cudaGetSymbolAddress((void**)&qlin, g_qlin);
    cudaGetSymbolAddress((void**)&klin, g_klin);
    cudaGetSymbolAddress((void**)&vlin, g_vlin);
    cudaGetSymbolAddress((void**)&q,    g_q);
    cudaGetSymbolAddress((void**)&k,    g_k);
    cudaGetSymbolAddress((void**)&v,    g_v);
    cudaGetSymbolAddress((void**)&att,  g_att);

    const int M = B_ * S_;  // 4096 tokens

    // projections (tf32 tensor-core GEMMs)
    gemm_tf32<<<dim3(H_ / 128, M / 128), 256>>>(hs, Wq, nullptr, qlin, M, H_, H_);
    gemm_tf32<<<dim3((NKV_ * HD_) / 128, M / 128), 256>>>(hs, Wk, bk, klin, M, NKV_ * HD_, H_);
    gemm_tf32<<<dim3((NKV_ * HD_) / 128, M / 128), 256>>>(hs, Wv, bv, vlin, M, NKV_ * HD_, H_);

    // rope + layout
    rope_kernel<<<(B_ * NH_ * S_ * HD_) / 256, 256>>>(qlin, cosb, sinb, q, NH_);
    rope_kernel<<<(B_ * NKV_ * S_ * HD_) / 256, 256>>>(klin, cosb, sinb, k, NKV_);
    vtrans_kernel<<<(B_ * NKV_ * S_ * HD_) / 256, 256>>>(vlin, v);

    // attention
    cudaFuncSetAttribute(attn_kernel, cudaFuncAttributeMaxDynamicSharedMemorySize, ATT_SMEM);
    attn_kernel<<<dim3(S_ / BQ, NH_, B_), 256, ATT_SMEM>>>(q, k, v, att);

    // output projection
    gemm_tf32<<<dim3(H_ / 128, M / 128), 256>>>(att, Wo, nullptr, out, M, H_, H_);
}

// round 3
// speedup vs baseline: 3.2177x; 1.9479x over previous
#include <cuda_runtime.h>
#include <math.h>

#define H_    4096
#define NH_   32
#define NKV_  8
#define HD_   128
#define S_    2048
#define B_    2
#define SCALE_ 0.08838834764831845f   // 128^-0.5

// ---------------- scratch (device globals; no allocations allowed) ----------
__device__ float g_qlin[(size_t)B_ * S_ * H_];            // 64 MB
__device__ float g_klin[(size_t)B_ * S_ * NKV_ * HD_];    // 16 MB
__device__ float g_vlin[(size_t)B_ * S_ * NKV_ * HD_];    // 16 MB
__device__ float g_q[(size_t)B_ * NH_ * S_ * HD_];        // 64 MB
__device__ float g_k[(size_t)B_ * NKV_ * S_ * HD_];       // 16 MB
__device__ float g_v[(size_t)B_ * NKV_ * S_ * HD_];       // 16 MB
__device__ float g_att[(size_t)B_ * S_ * H_];             // 64 MB

// ---------------- tf32 helpers ----------------------------------------------
__device__ __forceinline__ unsigned f2tf32(float f) {
    unsigned r;
    asm("cvt.rna.tf32.f32 %0, %1;" : "=r"(r) : "f"(f));
    return r;
}

__device__ __forceinline__ void mma_tf32(float c[4], const unsigned a[4], const unsigned b[2]) {
    asm volatile(
        "mma.sync.aligned.m16n8k8.row.col.f32.tf32.tf32.f32 "
        "{%0,%1,%2,%3}, {%4,%5,%6,%7}, {%8,%9}, {%0,%1,%2,%3};\n"
        : "+f"(c[0]), "+f"(c[1]), "+f"(c[2]), "+f"(c[3])
        : "r"(a[0]), "r"(a[1]), "r"(a[2]), "r"(a[3]), "r"(b[0]), "r"(b[1]));
}

// ---------------- TF32 GEMM: C[M,N] = A[M,K] @ B[N,K]^T (+bias) -------------
// block tile 128x128, k-tile 16, 256 threads = 8 warps (2m x 4n), warp 64x32
#define SAS 20   // smem row stride (words); conflict-free for frag pattern

__global__ __launch_bounds__(256) void gemm_tf32(
    const float* __restrict__ A, const float* __restrict__ Bm,
    const float* __restrict__ bias, float* __restrict__ C,
    int M, int N, int K)
{
    __shared__ unsigned As[128 * SAS];
    __shared__ unsigned Bs[128 * SAS];

    int tid = threadIdx.x;
    int warp = tid >> 5, lane = tid & 31;
    int r = lane >> 2, cq = lane & 3;
    int wm = (warp >> 2) * 64, wn = (warp & 3) * 32;
    int bm = blockIdx.y * 128, bn = blockIdx.x * 128;

    float acc[4][4][4];
#pragma unroll
    for (int mi = 0; mi < 4; mi++)
#pragma unroll
        for (int ni = 0; ni < 4; ni++)
#pragma unroll
            for (int t = 0; t < 4; t++) acc[mi][ni][t] = 0.f;

    int row0 = tid >> 2,         c40 = (tid & 3) << 2;
    int row1 = (tid + 256) >> 2, c41 = ((tid + 256) & 3) << 2;

    const float* Ab = A + (size_t)bm * K;
    const float* Bb = Bm + (size_t)bn * K;

    float4 pa0, pa1, pb0, pb1;
    pa0 = *(const float4*)(Ab + (size_t)row0 * K + c40);
    pa1 = *(const float4*)(Ab + (size_t)row1 * K + c41);
    pb0 = *(const float4*)(Bb + (size_t)row0 * K + c40);
    pb1 = *(const float4*)(Bb + (size_t)row1 * K + c41);

    int ntiles = K >> 4;
    for (int kt = 0; kt < ntiles; kt++) {
        As[row0 * SAS + c40 + 0] = f2tf32(pa0.x);
        As[row0 * SAS + c40 + 1] = f2tf32(pa0.y);
        As[row0 * SAS + c40 + 2] = f2tf32(pa0.z);
        As[row0 * SAS + c40 + 3] = f2tf32(pa0.w);
        As[row1 * SAS + c41 + 0] = f2tf32(pa1.x);
        As[row1 * SAS + c41 + 1] = f2tf32(pa1.y);
        As[row1 * SAS + c41 + 2] = f2tf32(pa1.z);
        As[row1 * SAS + c41 + 3] = f2tf32(pa1.w);
        Bs[row0 * SAS + c40 + 0] = f2tf32(pb0.x);
        Bs[row0 * SAS + c40 + 1] = f2tf32(pb0.y);
        Bs[row0 * SAS + c40 + 2] = f2tf32(pb0.z);
        Bs[row0 * SAS + c40 + 3] = f2tf32(pb0.w);
        Bs[row1 * SAS + c41 + 0] = f2tf32(pb1.x);
        Bs[row1 * SAS + c41 + 1] = f2tf32(pb1.y);
        Bs[row1 * SAS + c41 + 2] = f2tf32(pb1.z);
        Bs[row1 * SAS + c41 + 3] = f2tf32(pb1.w);
        __syncthreads();

        if (kt + 1 < ntiles) {
            int k0 = (kt + 1) << 4;
            pa0 = *(const float4*)(Ab + (size_t)row0 * K + k0 + c40);
            pa1 = *(const float4*)(Ab + (size_t)row1 * K + k0 + c41);
            pb0 = *(const float4*)(Bb + (size_t)row0 * K + k0 + c40);
            pb1 = *(const float4*)(Bb + (size_t)row1 * K + k0 + c41);
        }

#pragma unroll
        for (int s = 0; s < 2; s++) {
            unsigned a[4][4], b[4][2];
#pragma unroll
            for (int mi = 0; mi < 4; mi++) {
                int base = (wm + mi * 16 + r) * SAS + s * 8 + cq;
                a[mi][0] = As[base];
                a[mi][1] = As[base + 8 * SAS];
                a[mi][2] = As[base + 4];
                a[mi][3] = As[base + 8 * SAS + 4];
            }
#pragma unroll
            for (int ni = 0; ni < 4; ni++) {
                int base = (wn + ni * 8 + r) * SAS + s * 8 + cq;
                b[ni][0] = Bs[base];
                b[ni][1] = Bs[base + 4];
            }
#pragma unroll
            for (int mi = 0; mi < 4; mi++)
#pragma unroll
                for (int ni = 0; ni < 4; ni++)
                    mma_tf32(acc[mi][ni], a[mi], b[ni]);
        }
        __syncthreads();
    }

#pragma unroll
    for (int mi = 0; mi < 4; mi++) {
#pragma unroll
        for (int ni = 0; ni < 4; ni++) {
            int row = bm + wm + mi * 16 + r;
            int col = bn + wn + ni * 8 + cq * 2;
            float b0 = 0.f, b1 = 0.f;
            if (bias) { b0 = bias[col]; b1 = bias[col + 1]; }
            float2 v0, v1;
            v0.x = acc[mi][ni][0] + b0; v0.y = acc[mi][ni][1] + b1;
            v1.x = acc[mi][ni][2] + b0; v1.y = acc[mi][ni][3] + b1;
            *(float2*)(C + (size_t)row * N + col) = v0;
            *(float2*)(C + (size_t)(row + 8) * N + col) = v1;
        }
    }
}

// ---------------- RoPE + head transpose:  [B,S,nh*HD] -> [B,nh,S,HD] --------
__global__ void rope_kernel(const float* __restrict__ X, const float* __restrict__ cs,
                            const float* __restrict__ sn, float* __restrict__ out,
                            int nheads)
{
    int idx = blockIdx.x * blockDim.x + threadIdx.x;
    int d  = idx & (HD_ - 1);
    int s  = (idx >> 7) & (S_ - 1);
    int bh = idx >> 18;
    int h  = bh % nheads;
    int b  = bh / nheads;
    const float* xp = X + (size_t)(b * S_ + s) * (nheads * HD_) + h * HD_;
    int dd = d & 63;
    float c = cs[s * 64 + dd], si = sn[s * 64 + dd];
    float x1 = xp[2 * dd], x2 = xp[2 * dd + 1];
    out[idx] = (d < 64) ? (x1 * c - x2 * si) : (x1 * si + x2 * c);
}

// ---------------- V head transpose ------------------------------------------
__global__ void vtrans_kernel(const float* __restrict__ X, float* __restrict__ out)
{
    int idx = blockIdx.x * blockDim.x + threadIdx.x;
    int d  = idx & (HD_ - 1);
    int s  = (idx >> 7) & (S_ - 1);
    int bh = idx >> 18;
    int h  = bh % NKV_;
    int b  = bh / NKV_;
    out[idx] = X[(size_t)(b * S_ + s) * (NKV_ * HD_) + h * HD_ + d];
}

// ---------------- Tensor-core flash attention (tf32) ------------------------
// BQ=128 rows/block, 8 warps x m16; BKV=64 per tile.
#define AQ  128
#define AKV 64
#define QKS 132   // Q/K smem row stride (words): banks 4r+cq, conflict-free
#define VSS 136   // V smem row stride: B-frag gather banks 8cq+r, conflict-free
#define PSS 68    // P smem row stride: banks 4r+cq, conflict-free

#define QS_OFF 0
#define KS_OFF (AQ * QKS)                    // 16896
#define VS_OFF (KS_OFF + AKV * QKS)          // 25344
#define PS_OFF (VS_OFF + AKV * VSS)          // 34048
#define ATT_WORDS (PS_OFF + AQ * PSS)        // 42752
#define ATT_SMEM (ATT_WORDS * 4)             // 171008 bytes

__global__ __launch_bounds__(256) void attn_tc_kernel(
    const float* __restrict__ Q,  // [B,NH,S,HD]
    const float* __restrict__ K,  // [B,NKV,S,HD]
    const float* __restrict__ V,  // [B,NKV,S,HD]
    float* __restrict__ O)        // [B,S,NH,HD]
{
    extern __shared__ unsigned smw[];
    unsigned* Qs = smw + QS_OFF;
    unsigned* Ks = smw + KS_OFF;
    unsigned* Vs = smw + VS_OFF;
    unsigned* Ps = smw + PS_OFF;

    int tid = threadIdx.x;
    int warp = tid >> 5, lane = tid & 31;
    int r = lane >> 2, cq = lane & 3;
    int m0 = warp * 16;

    int qt = blockIdx.x, h = blockIdx.y, b = blockIdx.z;
    int kvh = h >> 2;
    const float* Qp = Q + (((size_t)b * NH_ + h) * S_ + qt * AQ) * HD_;
    const float* Kp = K + ((size_t)b * NKV_ + kvh) * S_ * HD_;
    const float* Vp = V + ((size_t)b * NKV_ + kvh) * S_ * HD_;

    // ---- load Q tile (scaled, tf32) ----
#pragma unroll
    for (int i = 0; i < 16; i++) {
        int fidx = tid + i * 256;            // 4096 float4
        int rr = fidx >> 5, c4 = (fidx & 31) << 2;
        float4 v = *(const float4*)(Qp + (size_t)rr * HD_ + c4);
        uint4 u;
        u.x = f2tf32(v.x * SCALE_); u.y = f2tf32(v.y * SCALE_);
        u.z = f2tf32(v.z * SCALE_); u.w = f2tf32(v.w * SCALE_);
        *(uint4*)&Qs[rr * QKS + c4] = u;
    }

    // softmax state (rows m0+r and m0+r+8)
    float mx0 = -1e30f, mx8 = -1e30f, l0 = 0.f, l8 = 0.f;
    // O accumulators: 16 n-tiles over HD
    float oa[16][4];
#pragma unroll
    for (int j = 0; j < 16; j++)
#pragma unroll
        for (int t = 0; t < 4; t++) oa[j][t] = 0.f;

    for (int kt = 0; kt < S_ / AKV; kt++) {
        __syncthreads();   // prior iteration's mma reads done
        const float* Kt = Kp + (size_t)kt * AKV * HD_;
        const float* Vt = Vp + (size_t)kt * AKV * HD_;
#pragma unroll
        for (int i = 0; i < 8; i++) {
            int fidx = tid + i * 256;        // 2048 float4
            int rr = fidx >> 5, c4 = (fidx & 31) << 2;
            float4 kv4 = *(const float4*)(Kt + (size_t)rr * HD_ + c4);
            uint4 ku;
            ku.x = f2tf32(kv4.x); ku.y = f2tf32(kv4.y);
            ku.z = f2tf32(kv4.z); ku.w = f2tf32(kv4.w);
            *(uint4*)&Ks[rr * QKS + c4] = ku;
            float4 vv4 = *(const float4*)(Vt + (size_t)rr * HD_ + c4);
            uint4 vu;
            vu.x = f2tf32(vv4.x); vu.y = f2tf32(vv4.y);
            vu.z = f2tf32(vv4.z); vu.w = f2tf32(vv4.w);
            *(uint4*)&Vs[rr * VSS + c4] = vu;
        }
        __syncthreads();

        // ---- scores: warp computes m16 x 64 ----
        float sc[8][4];
#pragma unroll
        for (int j = 0; j < 8; j++)
#pragma unroll
            for (int t = 0; t < 4; t++) sc[j][t] = 0.f;

#pragma unroll
        for (int k8 = 0; k8 < 16; k8++) {
            int k = k8 * 8;
            unsigned a[4];
            int abase = (m0 + r) * QKS + k + cq;
            a[0] = Qs[abase];
            a[1] = Qs[abase + 8 * QKS];
            a[2] = Qs[abase + 4];
            a[3] = Qs[abase + 8 * QKS + 4];
#pragma unroll
            for (int j = 0; j < 8; j++) {
                unsigned bfr[2];
                int bbase = (j * 8 + r) * QKS + k + cq;
                bfr[0] = Ks[bbase];
                bfr[1] = Ks[bbase + 4];
                mma_tf32(sc[j], a, bfr);
            }
        }

        // ---- online softmax (rows r and r+8, fully in-warp) ----
        float tm0 = -1e30f, tm8 = -1e30f;
#pragma unroll
        for (int j = 0; j < 8; j++) {
            tm0 = fmaxf(tm0, fmaxf(sc[j][0], sc[j][1]));
            tm8 = fmaxf(tm8, fmaxf(sc[j][2], sc[j][3]));
        }
        tm0 = fmaxf(tm0, __shfl_xor_sync(0xffffffffu, tm0, 1));
        tm0 = fmaxf(tm0, __shfl_xor_sync(0xffffffffu, tm0, 2));
        tm8 = fmaxf(tm8, __shfl_xor_sync(0xffffffffu, tm8, 1));
        tm8 = fmaxf(tm8, __shfl_xor_sync(0xffffffffu, tm8, 2));

        float nm0 = fmaxf(mx0, tm0), nm8 = fmaxf(mx8, tm8);
        float cr0 = __expf(mx0 - nm0), cr8 = __expf(mx8 - nm8);
        mx0 = nm0; mx8 = nm8;

        float rs0 = 0.f, rs8 = 0.f;
#pragma unroll
        for (int j = 0; j < 8; j++) {
            float p0 = __expf(sc[j][0] - nm0);
            float p1 = __expf(sc[j][1] - nm0);
            float p2 = __expf(sc[j][2] - nm8);
            float p3 = __expf(sc[j][3] - nm8);
            rs0 += p0 + p1; rs8 += p2 + p3;
            int col = j * 8 + cq * 2;
            Ps[(m0 + r) * PSS + col]     = f2tf32(p0);
            Ps[(m0 + r) * PSS + col + 1] = f2tf32(p1);
            Ps[(m0 + r + 8) * PSS + col]     = f2tf32(p2);
            Ps[(m0 + r + 8) * PSS + col + 1] = f2tf32(p3);
        }
        rs0 += __shfl_xor_sync(0xffffffffu, rs0, 1);
        rs0 += __shfl_xor_sync(0xffffffffu, rs0, 2);
        rs8 += __shfl_xor_sync(0xffffffffu, rs8, 1);
        rs8 += __shfl_xor_sync(0xffffffffu, rs8, 2);
        l0 = l0 * cr0 + rs0;
        l8 = l8 * cr8 + rs8;

#pragma unroll
        for (int j = 0; j < 16; j++) {
            oa[j][0] *= cr0; oa[j][1] *= cr0;
            oa[j][2] *= cr8; oa[j][3] *= cr8;
        }
        __syncwarp();

        // ---- PV: O(m16 x HD) += P(m16 x 64) @ V(64 x HD) ----
#pragma unroll
        for (int kk8 = 0; kk8 < 8; kk8++) {
            int kk = kk8 * 8;
            unsigned a[4];
            int abase = (m0 + r) * PSS + kk + cq;
            a[0] = Ps[abase];
            a[1] = Ps[abase + 8 * PSS];
            a[2] = Ps[abase + 4];
            a[3] = Ps[abase + 8 * PSS + 4];
#pragma unroll
            for (int j = 0; j < 16; j++) {
                unsigned bfr[2];
                // B[n][k] = V^T[n=8j+r][k=kk+cq] = Vs[(kk+cq)][8j+r]
                bfr[0] = Vs[(kk + cq) * VSS + j * 8 + r];
                bfr[1] = Vs[(kk + cq + 4) * VSS + j * 8 + r];
                mma_tf32(oa[j], a, bfr);
            }
        }
    }

    // ---- epilogue ----
    float inv0 = 1.f / l0, inv8 = 1.f / l8;
    int row0g = qt * AQ + m0 + r;
    int row8g = row0g + 8;
#pragma unroll
    for (int j = 0; j < 16; j++) {
        int col = j * 8 + cq * 2;
        float2 v0, v1;
        v0.x = oa[j][0] * inv0; v0.y = oa[j][1] * inv0;
        v1.x = oa[j][2] * inv8; v1.y = oa[j][3] * inv8;
        *(float2*)(O + (((size_t)b * S_ + row0g) * NH_ + h) * HD_ + col) = v0;
        *(float2*)(O + (((size_t)b * S_ + row8g) * NH_ + h) * HD_ + col) = v1;
    }
}

// ---------------- launcher ---------------------------------------------------
extern "C" void kernel_launch(void* const* d_in, const int* in_sizes, int n_in,
                              void* d_out, int out_size)
{
    const float* hs   = (const float*)d_in[0];
    const float* cosb = (const float*)d_in[1];
    const float* sinb = (const float*)d_in[2];
    const float* Wq   = (const float*)d_in[3];
    const float* Wk   = (const float*)d_in[4];
    const float* bk   = (const float*)d_in[5];
    const float* Wv   = (const float*)d_in[6];
    const float* bv   = (const float*)d_in[7];
    const float* Wo   = (const float*)d_in[8];
    float* out = (float*)d_out;

    float *qlin, *klin, *vlin, *q, *k, *v, *att;
    cudaGetSymbolAddress((void**)&qlin, g_qlin);
    cudaGetSymbolAddress((void**)&klin, g_klin);
    cudaGetSymbolAddress((void**)&vlin, g_vlin);
    cudaGetSymbolAddress((void**)&q,    g_q);
    cudaGetSymbolAddress((void**)&k,    g_k);
    cudaGetSymbolAddress((void**)&v,    g_v);
    cudaGetSymbolAddress((void**)&att,  g_att);

    const int M = B_ * S_;  // 4096 tokens

    // projections (tf32 tensor-core GEMMs)
    gemm_tf32<<<dim3(H_ / 128, M / 128), 256>>>(hs, Wq, nullptr, qlin, M, H_, H_);
    gemm_tf32<<<dim3((NKV_ * HD_) / 128, M / 128), 256>>>(hs, Wk, bk, klin, M, NKV_ * HD_, H_);
    gemm_tf32<<<dim3((NKV_ * HD_) / 128, M / 128), 256>>>(hs, Wv, bv, vlin, M, NKV_ * HD_, H_);

    // rope + layout
    rope_kernel<<<(B_ * NH_ * S_ * HD_) / 256, 256>>>(qlin, cosb, sinb, q, NH_);
    rope_kernel<<<(B_ * NKV_ * S_ * HD_) / 256, 256>>>(klin, cosb, sinb, k, NKV_);
    vtrans_kernel<<<(B_ * NKV_ * S_ * HD_) / 256, 256>>>(vlin, v);

    // attention (tensor-core tf32)
    cudaFuncSetAttribute(attn_tc_kernel, cudaFuncAttributeMaxDynamicSharedMemorySize, ATT_SMEM);
    attn_tc_kernel<<<dim3(S_ / AQ, NH_, B_), 256, ATT_SMEM>>>(q, k, v, att);

    // output projection
    gemm_tf32<<<dim3(H_ / 128, M / 128), 256>>>(att, Wo, nullptr, out, M, H_, H_);
}

// round 4
// speedup vs baseline: 3.8362x; 1.1922x over previous
#include <cuda_runtime.h>
#include <math.h>

#define H_    4096
#define NH_   32
#define NKV_  8
#define HD_   128
#define S_    2048
#define B_    2
#define SCALE_ 0.08838834764831845f   // 128^-0.5

// ---------------- scratch (device globals; no allocations allowed) ----------
__device__ float    g_qlin[(size_t)B_ * S_ * H_];            // fp32
__device__ float    g_klin[(size_t)B_ * S_ * NKV_ * HD_];
__device__ float    g_vlin[(size_t)B_ * S_ * NKV_ * HD_];
__device__ float    g_q[(size_t)B_ * NH_ * S_ * HD_];
__device__ float    g_k[(size_t)B_ * NKV_ * S_ * HD_];
__device__ float    g_v[(size_t)B_ * NKV_ * S_ * HD_];
__device__ unsigned g_hs_t[(size_t)B_ * S_ * H_];            // tf32 bits
__device__ unsigned g_wq_t[(size_t)H_ * H_];
__device__ unsigned g_wk_t[(size_t)NKV_ * HD_ * H_];
__device__ unsigned g_wv_t[(size_t)NKV_ * HD_ * H_];
__device__ unsigned g_wo_t[(size_t)H_ * H_];
__device__ unsigned g_att_t[(size_t)B_ * S_ * H_];           // attention out, tf32 bits

// ---------------- tf32 helpers ----------------------------------------------
__device__ __forceinline__ unsigned f2tf32(float f) {
    unsigned r;
    asm("cvt.rna.tf32.f32 %0, %1;" : "=r"(r) : "f"(f));
    return r;
}

__device__ __forceinline__ void mma_tf32(float c[4], const unsigned a[4], const unsigned b[2]) {
    asm volatile(
        "mma.sync.aligned.m16n8k8.row.col.f32.tf32.tf32.f32 "
        "{%0,%1,%2,%3}, {%4,%5,%6,%7}, {%8,%9}, {%0,%1,%2,%3};\n"
        : "+f"(c[0]), "+f"(c[1]), "+f"(c[2]), "+f"(c[3])
        : "r"(a[0]), "r"(a[1]), "r"(a[2]), "r"(a[3]), "r"(b[0]), "r"(b[1]));
}

__device__ __forceinline__ unsigned smem_u32(const void* p) {
    return (unsigned)__cvta_generic_to_shared(p);
}

// ---------------- convert fp32 -> tf32 bits ---------------------------------
__global__ __launch_bounds__(256) void cvt_tf32_kernel(
    const float4* __restrict__ in, uint4* __restrict__ out, int n4)
{
    int i = blockIdx.x * blockDim.x + threadIdx.x;
    if (i < n4) {
        float4 v = in[i];
        uint4 u;
        u.x = f2tf32(v.x); u.y = f2tf32(v.y);
        u.z = f2tf32(v.z); u.w = f2tf32(v.w);
        out[i] = u;
    }
}

// ---------------- pipelined tf32 GEMM: C = A @ B^T (+bias) ------------------
// A, B pre-converted tf32 bits. 128x128x32 tiles, cp.async 2-stage,
// 8 warps (2m x 4n), warp 64x32, 2 CTAs/SM.
#define GST 36                    // smem row stride (words), 36 % 32 == 4
#define GSTAGE (128 * GST)        // words per operand per stage
#define GEMM_SMEM (2 * 2 * GSTAGE * 4)   // 73728 bytes

__global__ __launch_bounds__(256, 2) void gemm_tf32p(
    const unsigned* __restrict__ A, const unsigned* __restrict__ Bm,
    const float* __restrict__ bias, float* __restrict__ C,
    int M, int N, int K)
{
    extern __shared__ unsigned sh[];

    int tid = threadIdx.x;
    int warp = tid >> 5, lane = tid & 31;
    int r = lane >> 2, cq = lane & 3;
    int wm = (warp >> 2) * 64, wn = (warp & 3) * 32;
    int bm = blockIdx.y * 128, bn = blockIdx.x * 128;

    float acc[4][4][4];
#pragma unroll
    for (int mi = 0; mi < 4; mi++)
#pragma unroll
        for (int ni = 0; ni < 4; ni++)
#pragma unroll
            for (int t = 0; t < 4; t++) acc[mi][ni][t] = 0.f;

    // cp.async indices: A tile 128 rows x 8 quads(16B), 1024 quads, 4/thread
    int qrow = tid >> 3, qq = (tid & 7) << 2;   // base row, quad col(word)

    const unsigned* Ab = A + (size_t)bm * K;
    const unsigned* Bb = Bm + (size_t)bn * K;

    // stage s: A at sh + s*2*GSTAGE, B at +GSTAGE
    auto load_stage = [&](int kt, int s) {
        unsigned* As = sh + s * 2 * GSTAGE;
        unsigned* Bs = As + GSTAGE;
        int k0 = kt << 5;
#pragma unroll
        for (int i = 0; i < 4; i++) {
            int row = qrow + i * 32;
            unsigned da = smem_u32(&As[row * GST + qq]);
            const unsigned* sa = Ab + (size_t)row * K + k0 + qq;
            asm volatile("cp.async.cg.shared.global [%0], [%1], 16;\n"
                         :: "r"(da), "l"(sa));
            unsigned db = smem_u32(&Bs[row * GST + qq]);
            const unsigned* sb = Bb + (size_t)row * K + k0 + qq;
            asm volatile("cp.async.cg.shared.global [%0], [%1], 16;\n"
                         :: "r"(db), "l"(sb));
        }
        asm volatile("cp.async.commit_group;\n");
    };

    int nt = K >> 5;
    load_stage(0, 0);

    for (int kt = 0; kt < nt; kt++) {
        if (kt + 1 < nt) {
            load_stage(kt + 1, (kt + 1) & 1);
            asm volatile("cp.async.wait_group 1;\n");
        } else {
            asm volatile("cp.async.wait_group 0;\n");
        }
        __syncthreads();

        unsigned* As = sh + (kt & 1) * 2 * GSTAGE;
        unsigned* Bs = As + GSTAGE;
#pragma unroll
        for (int k = 0; k < 32; k += 8) {
            unsigned a[4][4], b[4][2];
#pragma unroll
            for (int mi = 0; mi < 4; mi++) {
                int base = (wm + mi * 16 + r) * GST + k + cq;
                a[mi][0] = As[base];
                a[mi][1] = As[base + 8 * GST];
                a[mi][2] = As[base + 4];
                a[mi][3] = As[base + 8 * GST + 4];
            }
#pragma unroll
            for (int ni = 0; ni < 4; ni++) {
                int base = (wn + ni * 8 + r) * GST + k + cq;
                b[ni][0] = Bs[base];
                b[ni][1] = Bs[base + 4];
            }
#pragma unroll
            for (int mi = 0; mi < 4; mi++)
#pragma unroll
                for (int ni = 0; ni < 4; ni++)
                    mma_tf32(acc[mi][ni], a[mi], b[ni]);
        }
        __syncthreads();
    }

    // epilogue
#pragma unroll
    for (int mi = 0; mi < 4; mi++) {
#pragma unroll
        for (int ni = 0; ni < 4; ni++) {
            int row = bm + wm + mi * 16 + r;
            int col = bn + wn + ni * 8 + cq * 2;
            float b0 = 0.f, b1 = 0.f;
            if (bias) { b0 = bias[col]; b1 = bias[col + 1]; }
            float2 v0, v1;
            v0.x = acc[mi][ni][0] + b0; v0.y = acc[mi][ni][1] + b1;
            v1.x = acc[mi][ni][2] + b0; v1.y = acc[mi][ni][3] + b1;
            *(float2*)(C + (size_t)row * N + col) = v0;
            *(float2*)(C + (size_t)(row + 8) * N + col) = v1;
        }
    }
}

// ---------------- RoPE + head transpose:  [B,S,nh*HD] -> [B,nh,S,HD] --------
__global__ void rope_kernel(const float* __restrict__ X, const float* __restrict__ cs,
                            const float* __restrict__ sn, float* __restrict__ out,
                            int nheads)
{
    int idx = blockIdx.x * blockDim.x + threadIdx.x;
    int d  = idx & (HD_ - 1);
    int s  = (idx >> 7) & (S_ - 1);
    int bh = idx >> 18;
    int h  = bh % nheads;
    int b  = bh / nheads;
    const float* xp = X + (size_t)(b * S_ + s) * (nheads * HD_) + h * HD_;
    int dd = d & 63;
    float c = cs[s * 64 + dd], si = sn[s * 64 + dd];
    float x1 = xp[2 * dd], x2 = xp[2 * dd + 1];
    out[idx] = (d < 64) ? (x1 * c - x2 * si) : (x1 * si + x2 * c);
}

// ---------------- V head transpose ------------------------------------------
__global__ void vtrans_kernel(const float* __restrict__ X, float* __restrict__ out)
{
    int idx = blockIdx.x * blockDim.x + threadIdx.x;
    int d  = idx & (HD_ - 1);
    int s  = (idx >> 7) & (S_ - 1);
    int bh = idx >> 18;
    int h  = bh % NKV_;
    int b  = bh / NKV_;
    out[idx] = X[(size_t)(b * S_ + s) * (NKV_ * HD_) + h * HD_ + d];
}

// ---------------- Tensor-core flash attention (tf32) ------------------------
#define AQ  128
#define AKV 64
#define QKS 132
#define VSS 136
#define PSS 68

#define QS_OFF 0
#define KS_OFF (AQ * QKS)
#define VS_OFF (KS_OFF + AKV * QKS)
#define PS_OFF (VS_OFF + AKV * VSS)
#define ATT_WORDS (PS_OFF + AQ * PSS)
#define ATT_SMEM (ATT_WORDS * 4)

__global__ __launch_bounds__(256) void attn_tc_kernel(
    const float* __restrict__ Q,  // [B,NH,S,HD]
    const float* __restrict__ K,  // [B,NKV,S,HD]
    const float* __restrict__ V,  // [B,NKV,S,HD]
    unsigned* __restrict__ O)     // [B,S,NH,HD] tf32 bits
{
    extern __shared__ unsigned smw[];
    unsigned* Qs = smw + QS_OFF;
    unsigned* Ks = smw + KS_OFF;
    unsigned* Vs = smw + VS_OFF;
    unsigned* Ps = smw + PS_OFF;

    int tid = threadIdx.x;
    int warp = tid >> 5, lane = tid & 31;
    int r = lane >> 2, cq = lane & 3;
    int m0 = warp * 16;

    int qt = blockIdx.x, h = blockIdx.y, b = blockIdx.z;
    int kvh = h >> 2;
    const float* Qp = Q + (((size_t)b * NH_ + h) * S_ + qt * AQ) * HD_;
    const float* Kp = K + ((size_t)b * NKV_ + kvh) * S_ * HD_;
    const float* Vp = V + ((size_t)b * NKV_ + kvh) * S_ * HD_;

#pragma unroll
    for (int i = 0; i < 16; i++) {
        int fidx = tid + i * 256;
        int rr = fidx >> 5, c4 = (fidx & 31) << 2;
        float4 v = *(const float4*)(Qp + (size_t)rr * HD_ + c4);
        uint4 u;
        u.x = f2tf32(v.x * SCALE_); u.y = f2tf32(v.y * SCALE_);
        u.z = f2tf32(v.z * SCALE_); u.w = f2tf32(v.w * SCALE_);
        *(uint4*)&Qs[rr * QKS + c4] = u;
    }

    float mx0 = -1e30f, mx8 = -1e30f, l0 = 0.f, l8 = 0.f;
    float oa[16][4];
#pragma unroll
    for (int j = 0; j < 16; j++)
#pragma unroll
        for (int t = 0; t < 4; t++) oa[j][t] = 0.f;

    for (int kt = 0; kt < S_ / AKV; kt++) {
        __syncthreads();
        const float* Kt = Kp + (size_t)kt * AKV * HD_;
        const float* Vt = Vp + (size_t)kt * AKV * HD_;
#pragma unroll
        for (int i = 0; i < 8; i++) {
            int fidx = tid + i * 256;
            int rr = fidx >> 5, c4 = (fidx & 31) << 2;
            float4 kv4 = *(const float4*)(Kt + (size_t)rr * HD_ + c4);
            uint4 ku;
            ku.x = f2tf32(kv4.x); ku.y = f2tf32(kv4.y);
            ku.z = f2tf32(kv4.z); ku.w = f2tf32(kv4.w);
            *(uint4*)&Ks[rr * QKS + c4] = ku;
            float4 vv4 = *(const float4*)(Vt + (size_t)rr * HD_ + c4);
            uint4 vu;
            vu.x = f2tf32(vv4.x); vu.y = f2tf32(vv4.y);
            vu.z = f2tf32(vv4.z); vu.w = f2tf32(vv4.w);
            *(uint4*)&Vs[rr * VSS + c4] = vu;
        }
        __syncthreads();

        float sc[8][4];
#pragma unroll
        for (int j = 0; j < 8; j++)
#pragma unroll
            for (int t = 0; t < 4; t++) sc[j][t] = 0.f;

#pragma unroll
        for (int k8 = 0; k8 < 16; k8++) {
            int k = k8 * 8;
            unsigned a[4];
            int abase = (m0 + r) * QKS + k + cq;
            a[0] = Qs[abase];
            a[1] = Qs[abase + 8 * QKS];
            a[2] = Qs[abase + 4];
            a[3] = Qs[abase + 8 * QKS + 4];
#pragma unroll
            for (int j = 0; j < 8; j++) {
                unsigned bfr[2];
                int bbase = (j * 8 + r) * QKS + k + cq;
                bfr[0] = Ks[bbase];
                bfr[1] = Ks[bbase + 4];
                mma_tf32(sc[j], a, bfr);
            }
        }

        float tm0 = -1e30f, tm8 = -1e30f;
#pragma unroll
        for (int j = 0; j < 8; j++) {
            tm0 = fmaxf(tm0, fmaxf(sc[j][0], sc[j][1]));
            tm8 = fmaxf(tm8, fmaxf(sc[j][2], sc[j][3]));
        }
        tm0 = fmaxf(tm0, __shfl_xor_sync(0xffffffffu, tm0, 1));
        tm0 = fmaxf(tm0, __shfl_xor_sync(0xffffffffu, tm0, 2));
        tm8 = fmaxf(tm8, __shfl_xor_sync(0xffffffffu, tm8, 1));
        tm8 = fmaxf(tm8, __shfl_xor_sync(0xffffffffu, tm8, 2));

        float nm0 = fmaxf(mx0, tm0), nm8 = fmaxf(mx8, tm8);
        float cr0 = __expf(mx0 - nm0), cr8 = __expf(mx8 - nm8);
        mx0 = nm0; mx8 = nm8;

        float rs0 = 0.f, rs8 = 0.f;
#pragma unroll
        for (int j = 0; j < 8; j++) {
            float p0 = __expf(sc[j][0] - nm0);
            float p1 = __expf(sc[j][1] - nm0);
            float p2 = __expf(sc[j][2] - nm8);
            float p3 = __expf(sc[j][3] - nm8);
            rs0 += p0 + p1; rs8 += p2 + p3;
            int col = j * 8 + cq * 2;
            Ps[(m0 + r) * PSS + col]     = f2tf32(p0);
            Ps[(m0 + r) * PSS + col + 1] = f2tf32(p1);
            Ps[(m0 + r + 8) * PSS + col]     = f2tf32(p2);
            Ps[(m0 + r + 8) * PSS + col + 1] = f2tf32(p3);
        }
        rs0 += __shfl_xor_sync(0xffffffffu, rs0, 1);
        rs0 += __shfl_xor_sync(0xffffffffu, rs0, 2);
        rs8 += __shfl_xor_sync(0xffffffffu, rs8, 1);
        rs8 += __shfl_xor_sync(0xffffffffu, rs8, 2);
        l0 = l0 * cr0 + rs0;
        l8 = l8 * cr8 + rs8;

#pragma unroll
        for (int j = 0; j < 16; j++) {
            oa[j][0] *= cr0; oa[j][1] *= cr0;
            oa[j][2] *= cr8; oa[j][3] *= cr8;
        }
        __syncwarp();

#pragma unroll
        for (int kk8 = 0; kk8 < 8; kk8++) {
            int kk = kk8 * 8;
            unsigned a[4];
            int abase = (m0 + r) * PSS + kk + cq;
            a[0] = Ps[abase];
            a[1] = Ps[abase + 8 * PSS];
            a[2] = Ps[abase + 4];
            a[3] = Ps[abase + 8 * PSS + 4];
#pragma unroll
            for (int j = 0; j < 16; j++) {
                unsigned bfr[2];
                bfr[0] = Vs[(kk + cq) * VSS + j * 8 + r];
                bfr[1] = Vs[(kk + cq + 4) * VSS + j * 8 + r];
                mma_tf32(oa[j], a, bfr);
            }
        }
    }

    float inv0 = 1.f / l0, inv8 = 1.f / l8;
    int row0g = qt * AQ + m0 + r;
    int row8g = row0g + 8;
#pragma unroll
    for (int j = 0; j < 16; j++) {
        int col = j * 8 + cq * 2;
        uint2 u0, u1;
        u0.x = f2tf32(oa[j][0] * inv0); u0.y = f2tf32(oa[j][1] * inv0);
        u1.x = f2tf32(oa[j][2] * inv8); u1.y = f2tf32(oa[j][3] * inv8);
        *(uint2*)(O + (((size_t)b * S_ + row0g) * NH_ + h) * HD_ + col) = u0;
        *(uint2*)(O + (((size_t)b * S_ + row8g) * NH_ + h) * HD_ + col) = u1;
    }
}

// ---------------- launcher ---------------------------------------------------
extern "C" void kernel_launch(void* const* d_in, const int* in_sizes, int n_in,
                              void* d_out, int out_size)
{
    const float* hs   = (const float*)d_in[0];
    const float* cosb = (const float*)d_in[1];
    const float* sinb = (const float*)d_in[2];
    const float* Wq   = (const float*)d_in[3];
    const float* Wk   = (const float*)d_in[4];
    const float* bk   = (const float*)d_in[5];
    const float* Wv   = (const float*)d_in[6];
    const float* bv   = (const float*)d_in[7];
    const float* Wo   = (const float*)d_in[8];
    float* out = (float*)d_out;

    float *qlin, *klin, *vlin, *q, *k, *v;
    unsigned *hs_t, *wq_t, *wk_t, *wv_t, *wo_t, *att_t;
    cudaGetSymbolAddress((void**)&qlin, g_qlin);
    cudaGetSymbolAddress((void**)&klin, g_klin);
    cudaGetSymbolAddress((void**)&vlin, g_vlin);
    cudaGetSymbolAddress((void**)&q,    g_q);
    cudaGetSymbolAddress((void**)&k,    g_k);
    cudaGetSymbolAddress((void**)&v,    g_v);
    cudaGetSymbolAddress((void**)&hs_t, g_hs_t);
    cudaGetSymbolAddress((void**)&wq_t, g_wq_t);
    cudaGetSymbolAddress((void**)&wk_t, g_wk_t);
    cudaGetSymbolAddress((void**)&wv_t, g_wv_t);
    cudaGetSymbolAddress((void**)&wo_t, g_wo_t);
    cudaGetSymbolAddress((void**)&att_t, g_att_t);

    const int M = B_ * S_;           // 4096
    const int NKVD = NKV_ * HD_;     // 1024

    // convert operands to tf32 bits
    int n4a = (M * H_) / 4;          // hs, Wq, Wo size
    int n4b = (NKVD * H_) / 4;       // Wk, Wv size
    cvt_tf32_kernel<<<n4a / 256, 256>>>((const float4*)hs, (uint4*)hs_t, n4a);
    cvt_tf32_kernel<<<n4a / 256, 256>>>((const float4*)Wq, (uint4*)wq_t, n4a);
    cvt_tf32_kernel<<<n4b / 256, 256>>>((const float4*)Wk, (uint4*)wk_t, n4b);
    cvt_tf32_kernel<<<n4b / 256, 256>>>((const float4*)Wv, (uint4*)wv_t, n4b);
    cvt_tf32_kernel<<<n4a / 256, 256>>>((const float4*)Wo, (uint4*)wo_t, n4a);

    // projections
    cudaFuncSetAttribute(gemm_tf32p, cudaFuncAttributeMaxDynamicSharedMemorySize, GEMM_SMEM);
    gemm_tf32p<<<dim3(H_ / 128, M / 128), 256, GEMM_SMEM>>>(hs_t, wq_t, nullptr, qlin, M, H_, H_);
    gemm_tf32p<<<dim3(NKVD / 128, M / 128), 256, GEMM_SMEM>>>(hs_t, wk_t, bk, klin, M, NKVD, H_);
    gemm_tf32p<<<dim3(NKVD / 128, M / 128), 256, GEMM_SMEM>>>(hs_t, wv_t, bv, vlin, M, NKVD, H_);

    // rope + layout
    rope_kernel<<<(B_ * NH_ * S_ * HD_) / 256, 256>>>(qlin, cosb, sinb, q, NH_);
    rope_kernel<<<(B_ * NKV_ * S_ * HD_) / 256, 256>>>(klin, cosb, sinb, k, NKV_);
    vtrans_kernel<<<(B_ * NKV_ * S_ * HD_) / 256, 256>>>(vlin, v);

    // attention (tensor-core tf32) -> tf32-bit output
    cudaFuncSetAttribute(attn_tc_kernel, cudaFuncAttributeMaxDynamicSharedMemorySize, ATT_SMEM);
    attn_tc_kernel<<<dim3(S_ / AQ, NH_, B_), 256, ATT_SMEM>>>(q, k, v, att_t);

    // output projection
    gemm_tf32p<<<dim3(H_ / 128, M / 128), 256, GEMM_SMEM>>>(att_t, wo_t, nullptr, out, M, H_, H_);
}

// round 6
// speedup vs baseline: 5.5559x; 1.4483x over previous
#include <cuda_runtime.h>
#include <cuda_fp16.h>
#include <math.h>

#define H_    4096
#define NH_   32
#define NKV_  8
#define HD_   128
#define S_    2048
#define B_    2
#define SCALE_ 0.08838834764831845f   // 128^-0.5

// ---------------- scratch (device globals; no allocations allowed) ----------
__device__ float    g_qlin[(size_t)B_ * S_ * H_];
__device__ float    g_klin[(size_t)B_ * S_ * NKV_ * HD_];
__device__ float    g_vlin[(size_t)B_ * S_ * NKV_ * HD_];
__device__ float    g_q[(size_t)B_ * NH_ * S_ * HD_];
__device__ float    g_k[(size_t)B_ * NKV_ * S_ * HD_];
__device__ float    g_v[(size_t)B_ * NKV_ * S_ * HD_];
__device__ __half   g_hs_h[(size_t)B_ * S_ * H_];
__device__ __half   g_wq_h[(size_t)H_ * H_];
__device__ __half   g_wk_h[(size_t)NKV_ * HD_ * H_];
__device__ __half   g_wv_h[(size_t)NKV_ * HD_ * H_];
__device__ __half   g_wo_h[(size_t)H_ * H_];
__device__ __half   g_att_h[(size_t)B_ * S_ * H_];

// ---------------- helpers ----------------------------------------------------
__device__ __forceinline__ unsigned f2tf32(float f) {
    unsigned r;
    asm("cvt.rna.tf32.f32 %0, %1;" : "=r"(r) : "f"(f));
    return r;
}

__device__ __forceinline__ void mma_tf32(float c[4], const unsigned a[4], const unsigned b[2]) {
    asm volatile(
        "mma.sync.aligned.m16n8k8.row.col.f32.tf32.tf32.f32 "
        "{%0,%1,%2,%3}, {%4,%5,%6,%7}, {%8,%9}, {%0,%1,%2,%3};\n"
        : "+f"(c[0]), "+f"(c[1]), "+f"(c[2]), "+f"(c[3])
        : "r"(a[0]), "r"(a[1]), "r"(a[2]), "r"(a[3]), "r"(b[0]), "r"(b[1]));
}

__device__ __forceinline__ void mma_f16(float c[4], const unsigned a[4], const unsigned b[2]) {
    asm volatile(
        "mma.sync.aligned.m16n8k16.row.col.f32.f16.f16.f32 "
        "{%0,%1,%2,%3}, {%4,%5,%6,%7}, {%8,%9}, {%0,%1,%2,%3};\n"
        : "+f"(c[0]), "+f"(c[1]), "+f"(c[2]), "+f"(c[3])
        : "r"(a[0]), "r"(a[1]), "r"(a[2]), "r"(a[3]), "r"(b[0]), "r"(b[1]));
}

__device__ __forceinline__ unsigned smem_u32(const void* p) {
    return (unsigned)__cvta_generic_to_shared(p);
}

// ---------------- convert fp32 -> fp16 ---------------------------------------
__global__ __launch_bounds__(256) void cvt_f16_kernel(
    const float4* __restrict__ in, uint2* __restrict__ out, int n4)
{
    int i = blockIdx.x * blockDim.x + threadIdx.x;
    if (i < n4) {
        float4 v = in[i];
        __half2 h0 = __floats2half2_rn(v.x, v.y);
        __half2 h1 = __floats2half2_rn(v.z, v.w);
        uint2 u;
        u.x = *(unsigned*)&h0;
        u.y = *(unsigned*)&h1;
        out[i] = u;
    }
}

// ---------------- pipelined fp16 GEMM: C = A @ B^T (+bias), f32 accum --------
// A, B fp16. 128x128x64 tiles, cp.async 2-stage, 8 warps (2m x 4n), warp 64x32.
#define GSTH 36                       // smem row stride (32-bit words); 36%32==4
#define GSTAGE_H (128 * GSTH)         // words per operand per stage
#define GEMM_SMEM_H (2 * 2 * GSTAGE_H * 4)   // 73728 bytes

__global__ __launch_bounds__(256, 2) void gemm_f16p(
    const __half* __restrict__ A, const __half* __restrict__ Bm,
    const float* __restrict__ bias, float* __restrict__ C,
    int M, int N, int K)
{
    extern __shared__ unsigned sh[];

    int tid = threadIdx.x;
    int warp = tid >> 5, lane = tid & 31;
    int r = lane >> 2, cq = lane & 3;
    int wm = (warp >> 2) * 64, wn = (warp & 3) * 32;
    int bm = blockIdx.y * 128, bn = blockIdx.x * 128;
    int Kw = K >> 1;                  // K in 32-bit words (half2)

    float acc[4][4][4];
#pragma unroll
    for (int mi = 0; mi < 4; mi++)
#pragma unroll
        for (int ni = 0; ni < 4; ni++)
#pragma unroll
            for (int t = 0; t < 4; t++) acc[mi][ni][t] = 0.f;

    // cp.async: tile = 128 rows x 32 words = 8 quads/row, 1024 quads, 4/thread
    int qrow = tid >> 3, qq = (tid & 7) << 2;

    const unsigned* Ab = (const unsigned*)A + (size_t)bm * Kw;
    const unsigned* Bb = (const unsigned*)Bm + (size_t)bn * Kw;

    auto load_stage = [&](int kt, int s) {
        unsigned* As = sh + s * 2 * GSTAGE_H;
        unsigned* Bs = As + GSTAGE_H;
        int k0 = kt << 5;             // word offset
#pragma unroll
        for (int i = 0; i < 4; i++) {
            int row = qrow + i * 32;
            unsigned da = smem_u32(&As[row * GSTH + qq]);
            const unsigned* sa = Ab + (size_t)row * Kw + k0 + qq;
            asm volatile("cp.async.cg.shared.global [%0], [%1], 16;\n" :: "r"(da), "l"(sa));
            unsigned db = smem_u32(&Bs[row * GSTH + qq]);
            const unsigned* sb = Bb + (size_t)row * Kw + k0 + qq;
            asm volatile("cp.async.cg.shared.global [%0], [%1], 16;\n" :: "r"(db), "l"(sb));
        }
        asm volatile("cp.async.commit_group;\n");
    };

    int nt = K >> 6;                  // 64 halves (32 words) per tile
    load_stage(0, 0);

    for (int kt = 0; kt < nt; kt++) {
        if (kt + 1 < nt) {
            load_stage(kt + 1, (kt + 1) & 1);
            asm volatile("cp.async.wait_group 1;\n");
        } else {
            asm volatile("cp.async.wait_group 0;\n");
        }
        __syncthreads();

        unsigned* As = sh + (kt & 1) * 2 * GSTAGE_H;
        unsigned* Bs = As + GSTAGE_H;
#pragma unroll
        for (int k = 0; k < 32; k += 8) {     // 4 k16 steps
            unsigned a[4][4], b[4][2];
#pragma unroll
            for (int mi = 0; mi < 4; mi++) {
                int base = (wm + mi * 16 + r) * GSTH + k + cq;
                a[mi][0] = As[base];
                a[mi][1] = As[base + 8 * GSTH];
                a[mi][2] = As[base + 4];
                a[mi][3] = As[base + 8 * GSTH + 4];
            }
#pragma unroll
            for (int ni = 0; ni < 4; ni++) {
                int base = (wn + ni * 8 + r) * GSTH + k + cq;
                b[ni][0] = Bs[base];
                b[ni][1] = Bs[base + 4];
            }
#pragma unroll
            for (int mi = 0; mi < 4; mi++)
#pragma unroll
                for (int ni = 0; ni < 4; ni++)
                    mma_f16(acc[mi][ni], a[mi], b[ni]);
        }
        __syncthreads();
    }

#pragma unroll
    for (int mi = 0; mi < 4; mi++) {
#pragma unroll
        for (int ni = 0; ni < 4; ni++) {
            int row = bm + wm + mi * 16 + r;
            int col = bn + wn + ni * 8 + cq * 2;
            float b0 = 0.f, b1 = 0.f;
            if (bias) { b0 = bias[col]; b1 = bias[col + 1]; }
            float2 v0, v1;
            v0.x = acc[mi][ni][0] + b0; v0.y = acc[mi][ni][1] + b1;
            v1.x = acc[mi][ni][2] + b0; v1.y = acc[mi][ni][3] + b1;
            *(float2*)(C + (size_t)row * N + col) = v0;
            *(float2*)(C + (size_t)(row + 8) * N + col) = v1;
        }
    }
}

// ---------------- RoPE + head transpose --------------------------------------
__global__ void rope_kernel(const float* __restrict__ X, const float* __restrict__ cs,
                            const float* __restrict__ sn, float* __restrict__ out,
                            int nheads)
{
    int idx = blockIdx.x * blockDim.x + threadIdx.x;
    int d  = idx & (HD_ - 1);
    int s  = (idx >> 7) & (S_ - 1);
    int bh = idx >> 18;
    int h  = bh % nheads;
    int b  = bh / nheads;
    const float* xp = X + (size_t)(b * S_ + s) * (nheads * HD_) + h * HD_;
    int dd = d & 63;
    float c = cs[s * 64 + dd], si = sn[s * 64 + dd];
    float x1 = xp[2 * dd], x2 = xp[2 * dd + 1];
    out[idx] = (d < 64) ? (x1 * c - x2 * si) : (x1 * si + x2 * c);
}

__global__ void vtrans_kernel(const float* __restrict__ X, float* __restrict__ out)
{
    int idx = blockIdx.x * blockDim.x + threadIdx.x;
    int d  = idx & (HD_ - 1);
    int s  = (idx >> 7) & (S_ - 1);
    int bh = idx >> 18;
    int h  = bh % NKV_;
    int b  = bh / NKV_;
    out[idx] = X[(size_t)(b * S_ + s) * (NKV_ * HD_) + h * HD_ + d];
}

// ---------------- Tensor-core flash attention (tf32) -> fp16 out -------------
#define AQ  128
#define AKV 64
#define QKS 132
#define VSS 136
#define PSS 68

#define QS_OFF 0
#define KS_OFF (AQ * QKS)
#define VS_OFF (KS_OFF + AKV * QKS)
#define PS_OFF (VS_OFF + AKV * VSS)
#define ATT_WORDS (PS_OFF + AQ * PSS)
#define ATT_SMEM (ATT_WORDS * 4)

__global__ __launch_bounds__(256) void attn_tc_kernel(
    const float* __restrict__ Q,  // [B,NH,S,HD]
    const float* __restrict__ K,  // [B,NKV,S,HD]
    const float* __restrict__ V,  // [B,NKV,S,HD]
    __half* __restrict__ O)       // [B,S,NH,HD] fp16
{
    extern __shared__ unsigned smw[];
    unsigned* Qs = smw + QS_OFF;
    unsigned* Ks = smw + KS_OFF;
    unsigned* Vs = smw + VS_OFF;
    unsigned* Ps = smw + PS_OFF;

    int tid = threadIdx.x;
    int warp = tid >> 5, lane = tid & 31;
    int r = lane >> 2, cq = lane & 3;
    int m0 = warp * 16;

    int qt = blockIdx.x, h = blockIdx.y, b = blockIdx.z;
    int kvh = h >> 2;
    const float* Qp = Q + (((size_t)b * NH_ + h) * S_ + qt * AQ) * HD_;
    const float* Kp = K + ((size_t)b * NKV_ + kvh) * S_ * HD_;
    const float* Vp = V + ((size_t)b * NKV_ + kvh) * S_ * HD_;

#pragma unroll
    for (int i = 0; i < 16; i++) {
        int fidx = tid + i * 256;
        int rr = fidx >> 5, c4 = (fidx & 31) << 2;
        float4 v = *(const float4*)(Qp + (size_t)rr * HD_ + c4);
        uint4 u;
        u.x = f2tf32(v.x * SCALE_); u.y = f2tf32(v.y * SCALE_);
        u.z = f2tf32(v.z * SCALE_); u.w = f2tf32(v.w * SCALE_);
        *(uint4*)&Qs[rr * QKS + c4] = u;
    }

    float mx0 = -1e30f, mx8 = -1e30f, l0 = 0.f, l8 = 0.f;
    float oa[16][4];
#pragma unroll
    for (int j = 0; j < 16; j++)
#pragma unroll
        for (int t = 0; t < 4; t++) oa[j][t] = 0.f;

    for (int kt = 0; kt < S_ / AKV; kt++) {
        __syncthreads();
        const float* Kt = Kp + (size_t)kt * AKV * HD_;
        const float* Vt = Vp + (size_t)kt * AKV * HD_;
#pragma unroll
        for (int i = 0; i < 8; i++) {
            int fidx = tid + i * 256;
            int rr = fidx >> 5, c4 = (fidx & 31) << 2;
            float4 kv4 = *(const float4*)(Kt + (size_t)rr * HD_ + c4);
            uint4 ku;
            ku.x = f2tf32(kv4.x); ku.y = f2tf32(kv4.y);
            ku.z = f2tf32(kv4.z); ku.w = f2tf32(kv4.w);
            *(uint4*)&Ks[rr * QKS + c4] = ku;
            float4 vv4 = *(const float4*)(Vt + (size_t)rr * HD_ + c4);
            uint4 vu;
            vu.x = f2tf32(vv4.x); vu.y = f2tf32(vv4.y);
            vu.z = f2tf32(vv4.z); vu.w = f2tf32(vv4.w);
            *(uint4*)&Vs[rr * VSS + c4] = vu;
        }
        __syncthreads();

        float sc[8][4];
#pragma unroll
        for (int j = 0; j < 8; j++)
#pragma unroll
            for (int t = 0; t < 4; t++) sc[j][t] = 0.f;

#pragma unroll
        for (int k8 = 0; k8 < 16; k8++) {
            int k = k8 * 8;
            unsigned a[4];
            int abase = (m0 + r) * QKS + k + cq;
            a[0] = Qs[abase];
            a[1] = Qs[abase + 8 * QKS];
            a[2] = Qs[abase + 4];
            a[3] = Qs[abase + 8 * QKS + 4];
#pragma unroll
            for (int j = 0; j < 8; j++) {
                unsigned bfr[2];
                int bbase = (j * 8 + r) * QKS + k + cq;
                bfr[0] = Ks[bbase];
                bfr[1] = Ks[bbase + 4];
                mma_tf32(sc[j], a, bfr);
            }
        }

        float tm0 = -1e30f, tm8 = -1e30f;
#pragma unroll
        for (int j = 0; j < 8; j++) {
            tm0 = fmaxf(tm0, fmaxf(sc[j][0], sc[j][1]));
            tm8 = fmaxf(tm8, fmaxf(sc[j][2], sc[j][3]));
        }
        tm0 = fmaxf(tm0, __shfl_xor_sync(0xffffffffu, tm0, 1));
        tm0 = fmaxf(tm0, __shfl_xor_sync(0xffffffffu, tm0, 2));
        tm8 = fmaxf(tm8, __shfl_xor_sync(0xffffffffu, tm8, 1));
        tm8 = fmaxf(tm8, __shfl_xor_sync(0xffffffffu, tm8, 2));

        float nm0 = fmaxf(mx0, tm0), nm8 = fmaxf(mx8, tm8);
        float cr0 = __expf(mx0 - nm0), cr8 = __expf(mx8 - nm8);
        mx0 = nm0; mx8 = nm8;

        float rs0 = 0.f, rs8 = 0.f;
#pragma unroll
        for (int j = 0; j < 8; j++) {
            float p0 = __expf(sc[j][0] - nm0);
            float p1 = __expf(sc[j][1] - nm0);
            float p2 = __expf(sc[j][2] - nm8);
            float p3 = __expf(sc[j][3] - nm8);
            rs0 += p0 + p1; rs8 += p2 + p3;
            int col = j * 8 + cq * 2;
            Ps[(m0 + r) * PSS + col]     = f2tf32(p0);
            Ps[(m0 + r) * PSS + col + 1] = f2tf32(p1);
            Ps[(m0 + r + 8) * PSS + col]     = f2tf32(p2);
            Ps[(m0 + r + 8) * PSS + col + 1] = f2tf32(p3);
        }
        rs0 += __shfl_xor_sync(0xffffffffu, rs0, 1);
        rs0 += __shfl_xor_sync(0xffffffffu, rs0, 2);
        rs8 += __shfl_xor_sync(0xffffffffu, rs8, 1);
        rs8 += __shfl_xor_sync(0xffffffffu, rs8, 2);
        l0 = l0 * cr0 + rs0;
        l8 = l8 * cr8 + rs8;

#pragma unroll
        for (int j = 0; j < 16; j++) {
            oa[j][0] *= cr0; oa[j][1] *= cr0;
            oa[j][2] *= cr8; oa[j][3] *= cr8;
        }
        __syncwarp();

#pragma unroll
        for (int kk8 = 0; kk8 < 8; kk8++) {
            int kk = kk8 * 8;
            unsigned a[4];
            int abase = (m0 + r) * PSS + kk + cq;
            a[0] = Ps[abase];
            a[1] = Ps[abase + 8 * PSS];
            a[2] = Ps[abase + 4];
            a[3] = Ps[abase + 8 * PSS + 4];
#pragma unroll
            for (int j = 0; j < 16; j++) {
                unsigned bfr[2];
                bfr[0] = Vs[(kk + cq) * VSS + j * 8 + r];
                bfr[1] = Vs[(kk + cq + 4) * VSS + j * 8 + r];
                mma_tf32(oa[j], a, bfr);
            }
        }
    }

    float inv0 = 1.f / l0, inv8 = 1.f / l8;
    int row0g = qt * AQ + m0 + r;
    int row8g = row0g + 8;
#pragma unroll
    for (int j = 0; j < 16; j++) {
        int col = j * 8 + cq * 2;
        __half2 h0 = __floats2half2_rn(oa[j][0] * inv0, oa[j][1] * inv0);
        __half2 h1 = __floats2half2_rn(oa[j][2] * inv8, oa[j][3] * inv8);
        *(__half2*)(O + (((size_t)b * S_ + row0g) * NH_ + h) * HD_ + col) = h0;
        *(__half2*)(O + (((size_t)b * S_ + row8g) * NH_ + h) * HD_ + col) = h1;
    }
}

// ---------------- launcher ----------------------------------------------------
extern "C" void kernel_launch(void* const* d_in, const int* in_sizes, int n_in,
                              void* d_out, int out_size)
{
    const float* hs   = (const float*)d_in[0];
    const float* cosb = (const float*)d_in[1];
    const float* sinb = (const float*)d_in[2];
    const float* Wq   = (const float*)d_in[3];
    const float* Wk   = (const float*)d_in[4];
    const float* bk   = (const float*)d_in[5];
    const float* Wv   = (const float*)d_in[6];
    const float* bv   = (const float*)d_in[7];
    const float* Wo   = (const float*)d_in[8];
    float* out = (float*)d_out;

    float *qlin, *klin, *vlin, *q, *k, *v;
    __half *hs_h, *wq_h, *wk_h, *wv_h, *wo_h, *att_h;
    cudaGetSymbolAddress((void**)&qlin, g_qlin);
    cudaGetSymbolAddress((void**)&klin, g_klin);
    cudaGetSymbolAddress((void**)&vlin, g_vlin);
    cudaGetSymbolAddress((void**)&q,    g_q);
    cudaGetSymbolAddress((void**)&k,    g_k);
    cudaGetSymbolAddress((void**)&v,    g_v);
    cudaGetSymbolAddress((void**)&hs_h, g_hs_h);
    cudaGetSymbolAddress((void**)&wq_h, g_wq_h);
    cudaGetSymbolAddress((void**)&wk_h, g_wk_h);
    cudaGetSymbolAddress((void**)&wv_h, g_wv_h);
    cudaGetSymbolAddress((void**)&wo_h, g_wo_h);
    cudaGetSymbolAddress((void**)&att_h, g_att_h);

    const int M = B_ * S_;           // 4096
    const int NKVD = NKV_ * HD_;     // 1024

    // convert operands to fp16
    int n4a = (M * H_) / 4;
    int n4b = (NKVD * H_) / 4;
    cvt_f16_kernel<<<n4a / 256, 256>>>((const float4*)hs, (uint2*)hs_h, n4a);
    cvt_f16_kernel<<<n4a / 256, 256>>>((const float4*)Wq, (uint2*)wq_h, n4a);
    cvt_f16_kernel<<<n4b / 256, 256>>>((const float4*)Wk, (uint2*)wk_h, n4b);
    cvt_f16_kernel<<<n4b / 256, 256>>>((const float4*)Wv, (uint2*)wv_h, n4b);
    cvt_f16_kernel<<<n4a / 256, 256>>>((const float4*)Wo, (uint2*)wo_h, n4a);

    // projections (fp16 tensor-core GEMMs, fp32 accumulate)
    cudaFuncSetAttribute(gemm_f16p, cudaFuncAttributeMaxDynamicSharedMemorySize, GEMM_SMEM_H);
    gemm_f16p<<<dim3(H_ / 128, M / 128), 256, GEMM_SMEM_H>>>(hs_h, wq_h, nullptr, qlin, M, H_, H_);
    gemm_f16p<<<dim3(NKVD / 128, M / 128), 256, GEMM_SMEM_H>>>(hs_h, wk_h, bk, klin, M, NKVD, H_);
    gemm_f16p<<<dim3(NKVD / 128, M / 128), 256, GEMM_SMEM_H>>>(hs_h, wv_h, bv, vlin, M, NKVD, H_);

    // rope + layout
    rope_kernel<<<(B_ * NH_ * S_ * HD_) / 256, 256>>>(qlin, cosb, sinb, q, NH_);
    rope_kernel<<<(B_ * NKV_ * S_ * HD_) / 256, 256>>>(klin, cosb, sinb, k, NKV_);
    vtrans_kernel<<<(B_ * NKV_ * S_ * HD_) / 256, 256>>>(vlin, v);

    // attention (tf32 tensor-core) -> fp16 output
    cudaFuncSetAttribute(attn_tc_kernel, cudaFuncAttributeMaxDynamicSharedMemorySize, ATT_SMEM);
    attn_tc_kernel<<<dim3(S_ / AQ, NH_, B_), 256, ATT_SMEM>>>(q, k, v, att_h);

    // output projection
    gemm_f16p<<<dim3(H_ / 128, M / 128), 256, GEMM_SMEM_H>>>(att_h, wo_h, nullptr, out, M, H_, H_);
}